// round 15
// baseline (speedup 1.0000x reference)
#include <cuda_runtime.h>
#include <cstdint>

#define NB 64
#define NL 64
#define NC 16
#define DM 450          // EMB(300) + 3*50
#define NTOK 8192       // 2 * B * L

typedef unsigned long long ull;

__device__ __forceinline__ ull pk2(float lo, float hi) {
    ull r; asm("mov.b64 %0, {%1, %2};" : "=l"(r) : "f"(lo), "f"(hi)); return r;
}
__device__ __forceinline__ void upk2(ull v, float& lo, float& hi) {
    asm("mov.b64 {%0, %1}, %2;" : "=f"(lo), "=f"(hi) : "l"(v));
}
__device__ __forceinline__ void fma2(ull& d, ull a, ull b) {
    asm("fma.rn.f32x2 %0, %1, %2, %0;" : "+l"(d) : "l"(a), "l"(b));
}

__device__ float g_x[(size_t)NTOK * DM];
__device__ float g_y[(size_t)NTOK * DM];
__device__ float g_M[60000];

// ---------------------------------------------------------------------------
// 1) Precompute char tables: M[k][v][f] = sum_ch cemb[v][ch] * w[f][ch][k]
// ---------------------------------------------------------------------------
__global__ void precomp_kernel(const float* __restrict__ cemb,
                               const float* __restrict__ w3,
                               const float* __restrict__ w4,
                               const float* __restrict__ w5) {
    int idx = blockIdx.x * blockDim.x + threadIdx.x;
    if (idx >= 60000) return;
    const float* W;
    int WD, local;
    if (idx < 15000)      { W = w3; WD = 3; local = idx; }
    else if (idx < 35000) { W = w4; WD = 4; local = idx - 15000; }
    else                  { W = w5; WD = 5; local = idx - 35000; }
    int f  = local % 50;
    int kv = local / 50;
    int v  = kv % 100;
    int k  = kv / 100;
    const float* e  = cemb + v * 64;
    const float* wp = W + (size_t)f * 64 * WD + k;
    float s = 0.f;
#pragma unroll 8
    for (int ch = 0; ch < 64; ch++) s += e[ch] * wp[ch * WD];
    g_M[idx] = s;
}

// ---------------------------------------------------------------------------
// 2) Embedding + char features -> g_x[tok][450]
// ---------------------------------------------------------------------------
__global__ void embed_kernel(const int* __restrict__ q1, const int* __restrict__ q2,
                             const int* __restrict__ q1c, const int* __restrict__ q2c,
                             const float* __restrict__ wemb,
                             const float* __restrict__ b3, const float* __restrict__ b4,
                             const float* __restrict__ b5) {
    int tok = blockIdx.x;
    int r   = tok >> 12;
    int li  = tok & 4095;
    const int* q  = r ? q2 : q1;
    const int* qc = r ? q2c : q1c;
    int tid = threadIdx.x;

    __shared__ int ids[16];
    if (tid < 16) ids[tid] = qc[li * 16 + tid];
    __syncthreads();

    float* xrow = g_x + (size_t)tok * DM;
    const float* we = wemb + (size_t)q[li] * 300;
    for (int i = tid; i < 300; i += blockDim.x) xrow[i] = we[i];

    int f = tid;
    if (f < 150) {
        int fi, base, wd;
        float bias;
        if (f < 50)       { wd = 3; fi = f;       base = 0;     bias = b3[fi]; }
        else if (f < 100) { wd = 4; fi = f - 50;  base = 15000; bias = b4[fi]; }
        else              { wd = 5; fi = f - 100; base = 35000; bias = b5[fi]; }
        float m = 0.f;
        int tout = 16 - wd + 1;
        for (int t = 0; t < tout; t++) {
            float h = bias;
            for (int k = 0; k < wd; k++)
                h += g_M[base + (k * 100 + ids[t + k]) * 50 + fi];
            m = fmaxf(m, h);
        }
        xrow[300 + f] = m;
    }
}

// ---------------------------------------------------------------------------
// 3) Highway: y = x @ W^T + b ; out = sig(y)*relu(y) + (1-sig(y))*x
//    M-pair f32x2, 128x64 tile, 256 thr, 4 CTA/SM => 1 wave.
//    A: As[k][m] native ull row-pairs (broadcast, conflict-free).
//    B: Bs2[n][2k] dup pairs read as LDS.128 (2 k's/load): 8-lane phases
//       with banks 4*tc = all distinct => conflict-free. Zero MOVs.
// ---------------------------------------------------------------------------
#define HBM 128
#define HBN 64
#define HBK 16
#define ASW 132   // As row stride
#define BSW 36    // Bs2 row stride (2*16 + 4); 16B-aligned rows

__global__ __launch_bounds__(256, 4) void highway_kernel(int dir,
        const float* __restrict__ W, const float* __restrict__ bias) {
    const float* X = dir ? g_y : g_x;
    float* OUT     = dir ? g_x : g_y;
    __shared__ float As[HBK][ASW];     // [k][m]
    __shared__ float Bs2[HBN][BSW];    // [n][2k] duplicated pairs
    int bm = blockIdx.y * HBM;
    int bn = blockIdx.x * HBN;
    int tid = threadIdx.x;
    int tm = (tid >> 4) * 8;   // 8 rows = 4 M-pairs
    int tc = tid & 15;         // cols tc + 16p, p = 0..3
    // acc[pair][p]: rows (tm+2*pair, tm+2*pair+1), col bn+tc+16p
    ull acc[4][4] = {};

    for (int k0 = 0; k0 < DM; k0 += HBK) {
        // A fill: 128 m x 8 k-pairs (float2, coalesced loads)
        for (int idx = tid; idx < HBM * 8; idx += 256) {
            int m = idx >> 3, kp = idx & 7;
            int kk = k0 + 2 * kp;
            float2 v = make_float2(0.f, 0.f);
            if (kk < DM) v = *(const float2*)&X[(size_t)(bm + m) * DM + kk];
            As[2 * kp][m]     = v.x;
            As[2 * kp + 1][m] = v.y;
        }
        // B fill: 64 n x 8 k-pairs, one float4 dup-store (conflict-free phases)
        for (int idx = tid; idx < HBN * 8; idx += 256) {
            int n = idx >> 3, kp = idx & 7;
            int kk = k0 + 2 * kp;
            int gn = bn + n;
            float2 v = make_float2(0.f, 0.f);
            if (gn < DM && kk < DM) v = *(const float2*)&W[(size_t)gn * DM + kk];
            *(float4*)&Bs2[n][4 * kp] = make_float4(v.x, v.x, v.y, v.y);
        }
        __syncthreads();
#pragma unroll
        for (int q = 0; q < HBK / 2; q++) {
            // B: 2 k's per LDS.128: (b_{2q},b_{2q}), (b_{2q+1},b_{2q+1})
            ulonglong2 b0 = *(const ulonglong2*)&Bs2[tc][4 * q];
            ulonglong2 b1 = *(const ulonglong2*)&Bs2[tc + 16][4 * q];
            ulonglong2 b2 = *(const ulonglong2*)&Bs2[tc + 32][4 * q];
            ulonglong2 b3 = *(const ulonglong2*)&Bs2[tc + 48][4 * q];
            {   // k = 2q
                ulonglong2 a0 = *(const ulonglong2*)&As[2 * q][tm];
                ulonglong2 a1 = *(const ulonglong2*)&As[2 * q][tm + 4];
                fma2(acc[0][0], a0.x, b0.x); fma2(acc[1][0], a0.y, b0.x);
                fma2(acc[2][0], a1.x, b0.x); fma2(acc[3][0], a1.y, b0.x);
                fma2(acc[0][1], a0.x, b1.x); fma2(acc[1][1], a0.y, b1.x);
                fma2(acc[2][1], a1.x, b1.x); fma2(acc[3][1], a1.y, b1.x);
                fma2(acc[0][2], a0.x, b2.x); fma2(acc[1][2], a0.y, b2.x);
                fma2(acc[2][2], a1.x, b2.x); fma2(acc[3][2], a1.y, b2.x);
                fma2(acc[0][3], a0.x, b3.x); fma2(acc[1][3], a0.y, b3.x);
                fma2(acc[2][3], a1.x, b3.x); fma2(acc[3][3], a1.y, b3.x);
            }
            {   // k = 2q+1
                ulonglong2 a0 = *(const ulonglong2*)&As[2 * q + 1][tm];
                ulonglong2 a1 = *(const ulonglong2*)&As[2 * q + 1][tm + 4];
                fma2(acc[0][0], a0.x, b0.y); fma2(acc[1][0], a0.y, b0.y);
                fma2(acc[2][0], a1.x, b0.y); fma2(acc[3][0], a1.y, b0.y);
                fma2(acc[0][1], a0.x, b1.y); fma2(acc[1][1], a0.y, b1.y);
                fma2(acc[2][1], a1.x, b1.y); fma2(acc[3][1], a1.y, b1.y);
                fma2(acc[0][2], a0.x, b2.y); fma2(acc[1][2], a0.y, b2.y);
                fma2(acc[2][2], a1.x, b2.y); fma2(acc[3][2], a1.y, b2.y);
                fma2(acc[0][3], a0.x, b3.y); fma2(acc[1][3], a0.y, b3.y);
                fma2(acc[2][3], a1.x, b3.y); fma2(acc[3][3], a1.y, b3.y);
            }
        }
        __syncthreads();
    }

#pragma unroll
    for (int pr = 0; pr < 4; pr++) {
        int m0 = bm + tm + 2 * pr;
#pragma unroll
        for (int p = 0; p < 4; p++) {
            int n = bn + tc + 16 * p;
            if (n < DM) {
                float y0, y1;
                upk2(acc[pr][p], y0, y1);
                float bb = bias[n];
                float yy = y0 + bb;
                float g  = 1.f / (1.f + __expf(-yy));
                float xv = X[(size_t)m0 * DM + n];
                OUT[(size_t)m0 * DM + n] = g * fmaxf(yy, 0.f) + (1.f - g) * xv;
                yy = y1 + bb;
                g  = 1.f / (1.f + __expf(-yy));
                xv = X[(size_t)(m0 + 1) * DM + n];
                OUT[(size_t)(m0 + 1) * DM + n] = g * fmaxf(yy, 0.f) + (1.f - g) * xv;
            }
        }
    }
}

// ---------------------------------------------------------------------------
// 4) Self-attention (proven). One block (512 thr) per batch.
//    In-place iter0 (x += att), iter1 writes att to dout.
// ---------------------------------------------------------------------------
__global__ __launch_bounds__(512) void attn_kernel(
        const int* __restrict__ q1_len, const int* __restrict__ q2_len,
        const float* __restrict__ attw, const float* __restrict__ attb,
        int it, int last, float* __restrict__ dout) {
    int batch = blockIdx.x;
    int r = batch >> 6, b = batch & 63;
    int len = (r ? q2_len : q1_len)[b];
    const float* aw = attw + it * (3 * DM);
    float ab = attb[it];
    float* X = g_x + (size_t)batch * 64 * DM;

    __shared__ float xsT[64][68];
    __shared__ float xw[64][68];
    __shared__ float s1[64], s2[64];

    int tid  = threadIdx.x;
    int warp = tid >> 5, lane = tid & 31;
    int ti  = warp * 4;
    int tj2 = lane * 2;

    if (tid < 64) { s1[tid] = 0.f; s2[tid] = 0.f; }

    ull acc[4] = {0, 0, 0, 0};

    // ---- Phase A: scores + s1/s2 over d-tiles ----
    for (int d0 = 0; d0 < DM; d0 += 64) {
        int dn = min(64, DM - d0);
        __syncthreads();
        for (int idx = tid; idx < 64 * 64; idx += 512) {
            int row = idx >> 6, d = idx & 63;
            float v  = (d < dn) ? X[row * DM + d0 + d] : 0.f;
            float wv = (d < dn) ? aw[2 * DM + d0 + d] : 0.f;
            xsT[d][row] = v;
            xw[d][row]  = v * wv;
        }
        __syncthreads();

#pragma unroll
        for (int rr = 0; rr < 4; rr++) {
            int row = ti + rr;
            float a1 = 0.f, a2 = 0.f;
            for (int d = lane; d < dn; d += 32) {
                float xv = xsT[d][row];
                a1 += xv * aw[d0 + d];
                a2 += xv * aw[DM + d0 + d];
            }
#pragma unroll
            for (int off = 16; off > 0; off >>= 1) {
                a1 += __shfl_down_sync(0xffffffffu, a1, off);
                a2 += __shfl_down_sync(0xffffffffu, a2, off);
            }
            if (lane == 0) { s1[row] += a1; s2[row] += a2; }
        }

#pragma unroll 4
        for (int d = 0; d < 64; d++) {
            float4 a4 = *(const float4*)&xsT[d][ti];
            ull bw = *(const ull*)&xw[d][tj2];
            fma2(acc[0], pk2(a4.x, a4.x), bw);
            fma2(acc[1], pk2(a4.y, a4.y), bw);
            fma2(acc[2], pk2(a4.z, a4.z), bw);
            fma2(acc[3], pk2(a4.w, a4.w), bw);
        }
    }
    __syncthreads();

    // ---- Phase B: softmax in-warp ----
    {
        float2 s2p = *(const float2*)&s2[tj2];
#pragma unroll
        for (int i = 0; i < 4; i++) {
            int row = ti + i;
            float base = s1[row] + ab;
            float v0, v1;
            upk2(acc[i], v0, v1);
            v0 += base + s2p.x;
            v1 += base + s2p.y;
            float l0 = (tj2     < len) ? v0 : -1e-9f;
            float l1 = (tj2 + 1 < len) ? v1 : -1e-9f;
            float mx = fmaxf(l0, l1);
#pragma unroll
            for (int off = 16; off > 0; off >>= 1)
                mx = fmaxf(mx, __shfl_xor_sync(0xffffffffu, mx, off));
            float e0 = __expf(l0 - mx), e1 = __expf(l1 - mx);
            float s = e0 + e1;
#pragma unroll
            for (int off = 16; off > 0; off >>= 1)
                s += __shfl_xor_sync(0xffffffffu, s, off);
            float inv = 1.f / s;
            xw[tj2][row]     = e0 * inv;
            xw[tj2 + 1][row] = e1 * inv;
        }
    }
    __syncthreads();

    // ---- Phase C: att = P @ x; out / residual ----
    float* xs = &xsT[0][0];
    for (int d0 = 0; d0 < DM; d0 += 64) {
        int dn = min(64, DM - d0);
        for (int idx = tid; idx < 64 * 32; idx += 512) {
            int row = idx >> 5, dp = idx & 31;
            float2 v = make_float2(0.f, 0.f);
            if (2 * dp < dn) v = *(const float2*)&X[row * DM + d0 + 2 * dp];
            *(float2*)&xs[row * 68 + 2 * dp] = v;
        }
        __syncthreads();
        ull acco[4] = {0, 0, 0, 0};
#pragma unroll 4
        for (int j = 0; j < 64; j++) {
            float4 p4 = *(const float4*)&xw[j][ti];
            ull xv = *(const ull*)&xs[j * 68 + tj2];
            fma2(acco[0], pk2(p4.x, p4.x), xv);
            fma2(acco[1], pk2(p4.y, p4.y), xv);
            fma2(acco[2], pk2(p4.z, p4.z), xv);
            fma2(acco[3], pk2(p4.w, p4.w), xv);
        }
        int d = d0 + tj2;
#pragma unroll
        for (int i = 0; i < 4; i++) {
            int row = ti + i;
            float o0, o1;
            upk2(acco[i], o0, o1);
            if (last) {
                if (d < DM)     dout[((size_t)batch * 64 + row) * DM + d]     = o0;
                if (d + 1 < DM) dout[((size_t)batch * 64 + row) * DM + d + 1] = o1;
            } else {
                float2 xv = *(const float2*)&xs[row * 68 + tj2];
                if (d < DM)     X[row * DM + d]     = o0 + xv.x;
                if (d + 1 < DM) X[row * DM + d + 1] = o1 + xv.y;
            }
        }
        __syncthreads();
    }
}

// ---------------------------------------------------------------------------
extern "C" void kernel_launch(void* const* d_in, const int* in_sizes, int n_in,
                              void* d_out, int out_size) {
    const int*   q1     = (const int*)d_in[0];
    const int*   q2     = (const int*)d_in[1];
    const int*   q1_len = (const int*)d_in[2];
    const int*   q2_len = (const int*)d_in[3];
    const int*   q1c    = (const int*)d_in[4];
    const int*   q2c    = (const int*)d_in[5];
    const float* wemb   = (const float*)d_in[6];
    const float* cemb   = (const float*)d_in[7];
    const float* cw3    = (const float*)d_in[8];
    const float* cb3    = (const float*)d_in[9];
    const float* cw4    = (const float*)d_in[10];
    const float* cb4    = (const float*)d_in[11];
    const float* cw5    = (const float*)d_in[12];
    const float* cb5    = (const float*)d_in[13];
    const float* hw_w   = (const float*)d_in[14];
    const float* hw_b   = (const float*)d_in[15];
    const float* attw   = (const float*)d_in[16];
    const float* attb   = (const float*)d_in[17];
    float* out = (float*)d_out;

    precomp_kernel<<<(60000 + 255) / 256, 256>>>(cemb, cw3, cw4, cw5);
    embed_kernel<<<NTOK, 160>>>(q1, q2, q1c, q2c, wemb, cb3, cb4, cb5);
    highway_kernel<<<dim3(8, 64), 256>>>(0, hw_w, hw_b);   // g_x -> g_y
    highway_kernel<<<dim3(8, 64), 256>>>(1, hw_w, hw_b);   // g_y -> g_x
    attn_kernel<<<128, 512>>>(q1_len, q2_len, attw, attb, 0, 0, out);
    attn_kernel<<<128, 512>>>(q1_len, q2_len, attw, attb, 1, 1, out);
}

// round 16
// speedup vs baseline: 1.3429x; 1.3429x over previous
#include <cuda_runtime.h>
#include <cstdint>

#define NB 64
#define NL 64
#define NC 16
#define DM 450          // EMB(300) + 3*50
#define NTOK 8192       // 2 * B * L

typedef unsigned long long ull;

__device__ __forceinline__ ull pk2(float lo, float hi) {
    ull r; asm("mov.b64 %0, {%1, %2};" : "=l"(r) : "f"(lo), "f"(hi)); return r;
}
__device__ __forceinline__ void upk2(ull v, float& lo, float& hi) {
    asm("mov.b64 {%0, %1}, %2;" : "=f"(lo), "=f"(hi) : "l"(v));
}
__device__ __forceinline__ void fma2(ull& d, ull a, ull b) {
    asm("fma.rn.f32x2 %0, %1, %2, %0;" : "+l"(d) : "l"(a), "l"(b));
}

__device__ float g_x[(size_t)NTOK * DM];
__device__ float g_y[(size_t)NTOK * DM];
__device__ float g_M[60000];

// ---------------------------------------------------------------------------
// 1) Precompute char tables: M[k][v][f] = sum_ch cemb[v][ch] * w[f][ch][k]
// ---------------------------------------------------------------------------
__global__ void precomp_kernel(const float* __restrict__ cemb,
                               const float* __restrict__ w3,
                               const float* __restrict__ w4,
                               const float* __restrict__ w5) {
    int idx = blockIdx.x * blockDim.x + threadIdx.x;
    if (idx >= 60000) return;
    const float* W;
    int WD, local;
    if (idx < 15000)      { W = w3; WD = 3; local = idx; }
    else if (idx < 35000) { W = w4; WD = 4; local = idx - 15000; }
    else                  { W = w5; WD = 5; local = idx - 35000; }
    int f  = local % 50;
    int kv = local / 50;
    int v  = kv % 100;
    int k  = kv / 100;
    const float* e  = cemb + v * 64;
    const float* wp = W + (size_t)f * 64 * WD + k;
    float s = 0.f;
#pragma unroll 8
    for (int ch = 0; ch < 64; ch++) s += e[ch] * wp[ch * WD];
    g_M[idx] = s;
}

// ---------------------------------------------------------------------------
// 2) Embedding + char features -> g_x[tok][450]
// ---------------------------------------------------------------------------
__global__ void embed_kernel(const int* __restrict__ q1, const int* __restrict__ q2,
                             const int* __restrict__ q1c, const int* __restrict__ q2c,
                             const float* __restrict__ wemb,
                             const float* __restrict__ b3, const float* __restrict__ b4,
                             const float* __restrict__ b5) {
    int tok = blockIdx.x;
    int r   = tok >> 12;
    int li  = tok & 4095;
    const int* q  = r ? q2 : q1;
    const int* qc = r ? q2c : q1c;
    int tid = threadIdx.x;

    __shared__ int ids[16];
    if (tid < 16) ids[tid] = qc[li * 16 + tid];
    __syncthreads();

    float* xrow = g_x + (size_t)tok * DM;
    const float* we = wemb + (size_t)q[li] * 300;
    for (int i = tid; i < 300; i += blockDim.x) xrow[i] = we[i];

    int f = tid;
    if (f < 150) {
        int fi, base, wd;
        float bias;
        if (f < 50)       { wd = 3; fi = f;       base = 0;     bias = b3[fi]; }
        else if (f < 100) { wd = 4; fi = f - 50;  base = 15000; bias = b4[fi]; }
        else              { wd = 5; fi = f - 100; base = 35000; bias = b5[fi]; }
        float m = 0.f;
        int tout = 16 - wd + 1;
        for (int t = 0; t < tout; t++) {
            float h = bias;
            for (int k = 0; k < wd; k++)
                h += g_M[base + (k * 100 + ids[t + k]) * 50 + fi];
            m = fmaxf(m, h);
        }
        xrow[300 + f] = m;
    }
}

// ---------------------------------------------------------------------------
// 3) Highway: y = x @ W^T + b ; out = sig(y)*relu(y) + (1-sig(y))*x
//    M-pair f32x2, 128x64 tile, 256 thr, 4 CTA/SM => 1 wave.
//    A: As[k][m] native ull row-pairs (broadcast LDS.128, conflict-free).
//    B: Bs2[n][2k] dup pairs, STRIDE 34: LDS.64 phase banks (2tc+2k,+1)
//       cover all 32 exactly -> conflict-free. Zero MOVs in mainloop.
// ---------------------------------------------------------------------------
#define HBM 128
#define HBN 64
#define HBK 16
#define ASW 132   // As row stride
#define BSW 34    // Bs2 row stride (2*16 + 2): kills the tc/tc+8 collision

__global__ __launch_bounds__(256, 4) void highway_kernel(int dir,
        const float* __restrict__ W, const float* __restrict__ bias) {
    const float* X = dir ? g_y : g_x;
    float* OUT     = dir ? g_x : g_y;
    __shared__ float As[HBK][ASW];     // [k][m]
    __shared__ float Bs2[HBN][BSW];    // [n][2k] duplicated pairs
    int bm = blockIdx.y * HBM;
    int bn = blockIdx.x * HBN;
    int tid = threadIdx.x;
    int tm = (tid >> 4) * 8;   // 8 rows = 4 M-pairs
    int tc = tid & 15;         // cols tc + 16p, p = 0..3
    // acc[pair][p]: rows (tm+2*pair, tm+2*pair+1), col bn+tc+16p
    ull acc[4][4] = {};

    for (int k0 = 0; k0 < DM; k0 += HBK) {
        // A fill: 128 m x 8 k-pairs (float2, coalesced loads)
        for (int idx = tid; idx < HBM * 8; idx += 256) {
            int m = idx >> 3, kp = idx & 7;
            int kk = k0 + 2 * kp;
            float2 v = make_float2(0.f, 0.f);
            if (kk < DM) v = *(const float2*)&X[(size_t)(bm + m) * DM + kk];
            As[2 * kp][m]     = v.x;
            As[2 * kp + 1][m] = v.y;
        }
        // B fill: 64 n x 8 k-pairs, dup via two float2 stores (phase-exact banks)
        for (int idx = tid; idx < HBN * 8; idx += 256) {
            int n = idx >> 3, kp = idx & 7;
            int kk = k0 + 2 * kp;
            int gn = bn + n;
            float2 v = make_float2(0.f, 0.f);
            if (gn < DM && kk < DM) v = *(const float2*)&W[(size_t)gn * DM + kk];
            *(float2*)&Bs2[n][4 * kp]     = make_float2(v.x, v.x);
            *(float2*)&Bs2[n][4 * kp + 2] = make_float2(v.y, v.y);
        }
        __syncthreads();
#pragma unroll
        for (int k = 0; k < HBK; k++) {
            ulonglong2 a0 = *(const ulonglong2*)&As[k][tm];       // pairs (tm,tm+1),(tm+2,tm+3)
            ulonglong2 a1 = *(const ulonglong2*)&As[k][tm + 4];   // pairs (tm+4..tm+7)
            ull b0 = *(const ull*)&Bs2[tc][2 * k];
            ull b1 = *(const ull*)&Bs2[tc + 16][2 * k];
            ull b2 = *(const ull*)&Bs2[tc + 32][2 * k];
            ull b3 = *(const ull*)&Bs2[tc + 48][2 * k];
            fma2(acc[0][0], a0.x, b0); fma2(acc[1][0], a0.y, b0);
            fma2(acc[2][0], a1.x, b0); fma2(acc[3][0], a1.y, b0);
            fma2(acc[0][1], a0.x, b1); fma2(acc[1][1], a0.y, b1);
            fma2(acc[2][1], a1.x, b1); fma2(acc[3][1], a1.y, b1);
            fma2(acc[0][2], a0.x, b2); fma2(acc[1][2], a0.y, b2);
            fma2(acc[2][2], a1.x, b2); fma2(acc[3][2], a1.y, b2);
            fma2(acc[0][3], a0.x, b3); fma2(acc[1][3], a0.y, b3);
            fma2(acc[2][3], a1.x, b3); fma2(acc[3][3], a1.y, b3);
        }
        __syncthreads();
    }

#pragma unroll
    for (int pr = 0; pr < 4; pr++) {
        int m0 = bm + tm + 2 * pr;
#pragma unroll
        for (int p = 0; p < 4; p++) {
            int n = bn + tc + 16 * p;
            if (n < DM) {
                float y0, y1;
                upk2(acc[pr][p], y0, y1);
                float bb = bias[n];
                float yy = y0 + bb;
                float g  = __fdividef(1.f, 1.f + __expf(-yy));
                float xv = X[(size_t)m0 * DM + n];
                OUT[(size_t)m0 * DM + n] = g * fmaxf(yy, 0.f) + (1.f - g) * xv;
                yy = y1 + bb;
                g  = __fdividef(1.f, 1.f + __expf(-yy));
                xv = X[(size_t)(m0 + 1) * DM + n];
                OUT[(size_t)(m0 + 1) * DM + n] = g * fmaxf(yy, 0.f) + (1.f - g) * xv;
            }
        }
    }
}

// ---------------------------------------------------------------------------
// 4) Self-attention (round-2 proven, byte-identical). One block/batch.
//    In-place iter0 (x += att), iter1 writes att to dout.
// ---------------------------------------------------------------------------
__global__ __launch_bounds__(512) void attn_kernel(
        const int* __restrict__ q1_len, const int* __restrict__ q2_len,
        const float* __restrict__ attw, const float* __restrict__ attb,
        int it, int last, float* __restrict__ dout) {
    int batch = blockIdx.x;
    int r = batch >> 6, b = batch & 63;
    int len = (r ? q2_len : q1_len)[b];
    const float* aw = attw + it * (3 * DM);
    float ab = attb[it];
    float* X = g_x + (size_t)batch * 64 * DM;

    __shared__ float xsT[64][68];
    __shared__ float xw[64][68];
    __shared__ float s1[64], s2[64];

    int tid  = threadIdx.x;
    int warp = tid >> 5, lane = tid & 31;
    int ti  = warp * 4;
    int tj2 = lane * 2;

    if (tid < 64) { s1[tid] = 0.f; s2[tid] = 0.f; }

    ull acc[4] = {0, 0, 0, 0};

    // ---- Phase A: scores + s1/s2 over d-tiles ----
    for (int d0 = 0; d0 < DM; d0 += 64) {
        int dn = min(64, DM - d0);
        __syncthreads();
        for (int idx = tid; idx < 64 * 64; idx += 512) {
            int row = idx >> 6, d = idx & 63;
            float v  = (d < dn) ? X[row * DM + d0 + d] : 0.f;
            float wv = (d < dn) ? aw[2 * DM + d0 + d] : 0.f;
            xsT[d][row] = v;
            xw[d][row]  = v * wv;
        }
        __syncthreads();

#pragma unroll
        for (int rr = 0; rr < 4; rr++) {
            int row = ti + rr;
            float a1 = 0.f, a2 = 0.f;
            for (int d = lane; d < dn; d += 32) {
                float xv = xsT[d][row];
                a1 += xv * aw[d0 + d];
                a2 += xv * aw[DM + d0 + d];
            }
#pragma unroll
            for (int off = 16; off > 0; off >>= 1) {
                a1 += __shfl_down_sync(0xffffffffu, a1, off);
                a2 += __shfl_down_sync(0xffffffffu, a2, off);
            }
            if (lane == 0) { s1[row] += a1; s2[row] += a2; }
        }

#pragma unroll 4
        for (int d = 0; d < 64; d++) {
            float4 a4 = *(const float4*)&xsT[d][ti];
            ull bw = *(const ull*)&xw[d][tj2];
            fma2(acc[0], pk2(a4.x, a4.x), bw);
            fma2(acc[1], pk2(a4.y, a4.y), bw);
            fma2(acc[2], pk2(a4.z, a4.z), bw);
            fma2(acc[3], pk2(a4.w, a4.w), bw);
        }
    }
    __syncthreads();

    // ---- Phase B: softmax in-warp ----
    {
        float2 s2p = *(const float2*)&s2[tj2];
#pragma unroll
        for (int i = 0; i < 4; i++) {
            int row = ti + i;
            float base = s1[row] + ab;
            float v0, v1;
            upk2(acc[i], v0, v1);
            v0 += base + s2p.x;
            v1 += base + s2p.y;
            float l0 = (tj2     < len) ? v0 : -1e-9f;
            float l1 = (tj2 + 1 < len) ? v1 : -1e-9f;
            float mx = fmaxf(l0, l1);
#pragma unroll
            for (int off = 16; off > 0; off >>= 1)
                mx = fmaxf(mx, __shfl_xor_sync(0xffffffffu, mx, off));
            float e0 = __expf(l0 - mx), e1 = __expf(l1 - mx);
            float s = e0 + e1;
#pragma unroll
            for (int off = 16; off > 0; off >>= 1)
                s += __shfl_xor_sync(0xffffffffu, s, off);
            float inv = 1.f / s;
            xw[tj2][row]     = e0 * inv;
            xw[tj2 + 1][row] = e1 * inv;
        }
    }
    __syncthreads();

    // ---- Phase C: att = P @ x; out / residual ----
    float* xs = &xsT[0][0];
    for (int d0 = 0; d0 < DM; d0 += 64) {
        int dn = min(64, DM - d0);
        for (int idx = tid; idx < 64 * 32; idx += 512) {
            int row = idx >> 5, dp = idx & 31;
            float2 v = make_float2(0.f, 0.f);
            if (2 * dp < dn) v = *(const float2*)&X[row * DM + d0 + 2 * dp];
            *(float2*)&xs[row * 68 + 2 * dp] = v;
        }
        __syncthreads();
        ull acco[4] = {0, 0, 0, 0};
#pragma unroll 4
        for (int j = 0; j < 64; j++) {
            float4 p4 = *(const float4*)&xw[j][ti];
            ull xv = *(const ull*)&xs[j * 68 + tj2];
            fma2(acco[0], pk2(p4.x, p4.x), xv);
            fma2(acco[1], pk2(p4.y, p4.y), xv);
            fma2(acco[2], pk2(p4.z, p4.z), xv);
            fma2(acco[3], pk2(p4.w, p4.w), xv);
        }
        int d = d0 + tj2;
#pragma unroll
        for (int i = 0; i < 4; i++) {
            int row = ti + i;
            float o0, o1;
            upk2(acco[i], o0, o1);
            if (last) {
                if (d < DM)     dout[((size_t)batch * 64 + row) * DM + d]     = o0;
                if (d + 1 < DM) dout[((size_t)batch * 64 + row) * DM + d + 1] = o1;
            } else {
                float2 xv = *(const float2*)&xs[row * 68 + tj2];
                if (d < DM)     X[row * DM + d]     = o0 + xv.x;
                if (d + 1 < DM) X[row * DM + d + 1] = o1 + xv.y;
            }
        }
        __syncthreads();
    }
}

// ---------------------------------------------------------------------------
extern "C" void kernel_launch(void* const* d_in, const int* in_sizes, int n_in,
                              void* d_out, int out_size) {
    const int*   q1     = (const int*)d_in[0];
    const int*   q2     = (const int*)d_in[1];
    const int*   q1_len = (const int*)d_in[2];
    const int*   q2_len = (const int*)d_in[3];
    const int*   q1c    = (const int*)d_in[4];
    const int*   q2c    = (const int*)d_in[5];
    const float* wemb   = (const float*)d_in[6];
    const float* cemb   = (const float*)d_in[7];
    const float* cw3    = (const float*)d_in[8];
    const float* cb3    = (const float*)d_in[9];
    const float* cw4    = (const float*)d_in[10];
    const float* cb4    = (const float*)d_in[11];
    const float* cw5    = (const float*)d_in[12];
    const float* cb5    = (const float*)d_in[13];
    const float* hw_w   = (const float*)d_in[14];
    const float* hw_b   = (const float*)d_in[15];
    const float* attw   = (const float*)d_in[16];
    const float* attb   = (const float*)d_in[17];
    float* out = (float*)d_out;

    precomp_kernel<<<(60000 + 255) / 256, 256>>>(cemb, cw3, cw4, cw5);
    embed_kernel<<<NTOK, 160>>>(q1, q2, q1c, q2c, wemb, cb3, cb4, cb5);
    highway_kernel<<<dim3(8, 64), 256>>>(0, hw_w, hw_b);   // g_x -> g_y
    highway_kernel<<<dim3(8, 64), 256>>>(1, hw_w, hw_b);   // g_y -> g_x
    attn_kernel<<<128, 512>>>(q1_len, q2_len, attw, attb, 0, 0, out);
    attn_kernel<<<128, 512>>>(q1_len, q2_len, attw, attb, 1, 1, out);
}

// round 17
// speedup vs baseline: 1.5364x; 1.1441x over previous
#include <cuda_runtime.h>
#include <cstdint>

#define NB 64
#define NL 64
#define NC 16
#define DM 450          // EMB(300) + 3*50
#define NTOK 8192       // 2 * B * L

typedef unsigned long long ull;

__device__ __forceinline__ ull pk2(float lo, float hi) {
    ull r; asm("mov.b64 %0, {%1, %2};" : "=l"(r) : "f"(lo), "f"(hi)); return r;
}
__device__ __forceinline__ void upk2(ull v, float& lo, float& hi) {
    asm("mov.b64 {%0, %1}, %2;" : "=f"(lo), "=f"(hi) : "l"(v));
}
__device__ __forceinline__ void fma2(ull& d, ull a, ull b) {
    asm("fma.rn.f32x2 %0, %1, %2, %0;" : "+l"(d) : "l"(a), "l"(b));
}

__device__ float g_x[(size_t)NTOK * DM];
__device__ float g_y[(size_t)NTOK * DM];
__device__ float g_M[60000];

// ---------------------------------------------------------------------------
// 1) Precompute char tables: M[k][v][f] = sum_ch cemb[v][ch] * w[f][ch][k]
// ---------------------------------------------------------------------------
__global__ void precomp_kernel(const float* __restrict__ cemb,
                               const float* __restrict__ w3,
                               const float* __restrict__ w4,
                               const float* __restrict__ w5) {
    int idx = blockIdx.x * blockDim.x + threadIdx.x;
    if (idx >= 60000) return;
    const float* W;
    int WD, local;
    if (idx < 15000)      { W = w3; WD = 3; local = idx; }
    else if (idx < 35000) { W = w4; WD = 4; local = idx - 15000; }
    else                  { W = w5; WD = 5; local = idx - 35000; }
    int f  = local % 50;
    int kv = local / 50;
    int v  = kv % 100;
    int k  = kv / 100;
    const float* e  = cemb + v * 64;
    const float* wp = W + (size_t)f * 64 * WD + k;
    float s = 0.f;
#pragma unroll 8
    for (int ch = 0; ch < 64; ch++) s += e[ch] * wp[ch * WD];
    g_M[idx] = s;
}

// ---------------------------------------------------------------------------
// 2) Embedding + char features -> g_x[tok][450]
// ---------------------------------------------------------------------------
__global__ void embed_kernel(const int* __restrict__ q1, const int* __restrict__ q2,
                             const int* __restrict__ q1c, const int* __restrict__ q2c,
                             const float* __restrict__ wemb,
                             const float* __restrict__ b3, const float* __restrict__ b4,
                             const float* __restrict__ b5) {
    int tok = blockIdx.x;
    int r   = tok >> 12;
    int li  = tok & 4095;
    const int* q  = r ? q2 : q1;
    const int* qc = r ? q2c : q1c;
    int tid = threadIdx.x;

    __shared__ int ids[16];
    if (tid < 16) ids[tid] = qc[li * 16 + tid];
    __syncthreads();

    float* xrow = g_x + (size_t)tok * DM;
    const float* we = wemb + (size_t)q[li] * 300;
    for (int i = tid; i < 300; i += blockDim.x) xrow[i] = we[i];

    int f = tid;
    if (f < 150) {
        int fi, base, wd;
        float bias;
        if (f < 50)       { wd = 3; fi = f;       base = 0;     bias = b3[fi]; }
        else if (f < 100) { wd = 4; fi = f - 50;  base = 15000; bias = b4[fi]; }
        else              { wd = 5; fi = f - 100; base = 35000; bias = b5[fi]; }
        float m = 0.f;
        int tout = 16 - wd + 1;
        for (int t = 0; t < tout; t++) {
            float h = bias;
            for (int k = 0; k < wd; k++)
                h += g_M[base + (k * 100 + ids[t + k]) * 50 + fi];
            m = fmaxf(m, h);
        }
        xrow[300 + f] = m;
    }
}

// ---------------------------------------------------------------------------
// 3) Highway: y = x @ W^T + b ; out = sig(y)*relu(y) + (1-sig(y))*x
//    M-pair f32x2, 128x64 tile, 256 thr, 4 CTA/SM => 1 wave.
//    A: As[k][m] native ull row-pairs (broadcast LDS.128, crossbar-cheap).
//    B: Bs[k][n] NATURAL, one float4/k (conflict-free, unique bytes only),
//       dup pairs built with 4 pk2 MOVs -> crossbar load halved vs dup-smem.
// ---------------------------------------------------------------------------
#define HBM 128
#define HBN 64
#define HBK 16
#define ASW 132   // As row stride
#define BSW 68    // Bs row stride (64 + 4)

__global__ __launch_bounds__(256, 4) void highway_kernel(int dir,
        const float* __restrict__ W, const float* __restrict__ bias) {
    const float* X = dir ? g_y : g_x;
    float* OUT     = dir ? g_x : g_y;
    __shared__ float As[HBK][ASW];    // [k][m]
    __shared__ float Bs[HBK][BSW];    // [k][n] natural
    int bm = blockIdx.y * HBM;
    int bn = blockIdx.x * HBN;
    int tid = threadIdx.x;
    int tm = (tid >> 4) * 8;   // 8 rows = 4 M-pairs
    int tn = (tid & 15) * 4;   // 4 consecutive cols
    // acc[pair][j]: rows (tm+2*pair, tm+2*pair+1), col bn+tn+j
    ull acc[4][4] = {};

    for (int k0 = 0; k0 < DM; k0 += HBK) {
        // A fill: 128 m x 8 k-pairs (float2, coalesced loads)
        for (int idx = tid; idx < HBM * 8; idx += 256) {
            int m = idx >> 3, kp = idx & 7;
            int kk = k0 + 2 * kp;
            float2 v = make_float2(0.f, 0.f);
            if (kk < DM) v = *(const float2*)&X[(size_t)(bm + m) * DM + kk];
            As[2 * kp][m]     = v.x;
            As[2 * kp + 1][m] = v.y;
        }
        // B fill: 64 n x 8 k-pairs, natural layout (coalesced global reads)
        for (int idx = tid; idx < HBN * 8; idx += 256) {
            int n = idx >> 3, kp = idx & 7;
            int kk = k0 + 2 * kp;
            int gn = bn + n;
            float2 v = make_float2(0.f, 0.f);
            if (gn < DM && kk < DM) v = *(const float2*)&W[(size_t)gn * DM + kk];
            Bs[2 * kp][n]     = v.x;
            Bs[2 * kp + 1][n] = v.y;
        }
        __syncthreads();
#pragma unroll
        for (int k = 0; k < HBK; k++) {
            ulonglong2 a0 = *(const ulonglong2*)&As[k][tm];       // pairs (tm,tm+1),(tm+2,tm+3)
            ulonglong2 a1 = *(const ulonglong2*)&As[k][tm + 4];   // pairs (tm+4..tm+7)
            float4 bv = *(const float4*)&Bs[k][tn];
            ull b0 = pk2(bv.x, bv.x);
            ull b1 = pk2(bv.y, bv.y);
            ull b2 = pk2(bv.z, bv.z);
            ull b3 = pk2(bv.w, bv.w);
            fma2(acc[0][0], a0.x, b0); fma2(acc[1][0], a0.y, b0);
            fma2(acc[2][0], a1.x, b0); fma2(acc[3][0], a1.y, b0);
            fma2(acc[0][1], a0.x, b1); fma2(acc[1][1], a0.y, b1);
            fma2(acc[2][1], a1.x, b1); fma2(acc[3][1], a1.y, b1);
            fma2(acc[0][2], a0.x, b2); fma2(acc[1][2], a0.y, b2);
            fma2(acc[2][2], a1.x, b2); fma2(acc[3][2], a1.y, b2);
            fma2(acc[0][3], a0.x, b3); fma2(acc[1][3], a0.y, b3);
            fma2(acc[2][3], a1.x, b3); fma2(acc[3][3], a1.y, b3);
        }
        __syncthreads();
    }

#pragma unroll
    for (int pr = 0; pr < 4; pr++) {
        int m0 = bm + tm + 2 * pr;
#pragma unroll
        for (int j = 0; j < 4; j++) {
            int n = bn + tn + j;
            if (n < DM) {
                float y0, y1;
                upk2(acc[pr][j], y0, y1);
                float bb = bias[n];
                float yy = y0 + bb;
                float g  = __fdividef(1.f, 1.f + __expf(-yy));
                float xv = X[(size_t)m0 * DM + n];
                OUT[(size_t)m0 * DM + n] = g * fmaxf(yy, 0.f) + (1.f - g) * xv;
                yy = y1 + bb;
                g  = __fdividef(1.f, 1.f + __expf(-yy));
                xv = X[(size_t)(m0 + 1) * DM + n];
                OUT[(size_t)(m0 + 1) * DM + n] = g * fmaxf(yy, 0.f) + (1.f - g) * xv;
            }
        }
    }
}

// ---------------------------------------------------------------------------
// 4) Self-attention (round-2 proven, byte-identical). One block/batch.
//    In-place iter0 (x += att), iter1 writes att to dout.
// ---------------------------------------------------------------------------
__global__ __launch_bounds__(512) void attn_kernel(
        const int* __restrict__ q1_len, const int* __restrict__ q2_len,
        const float* __restrict__ attw, const float* __restrict__ attb,
        int it, int last, float* __restrict__ dout) {
    int batch = blockIdx.x;
    int r = batch >> 6, b = batch & 63;
    int len = (r ? q2_len : q1_len)[b];
    const float* aw = attw + it * (3 * DM);
    float ab = attb[it];
    float* X = g_x + (size_t)batch * 64 * DM;

    __shared__ float xsT[64][68];
    __shared__ float xw[64][68];
    __shared__ float s1[64], s2[64];

    int tid  = threadIdx.x;
    int warp = tid >> 5, lane = tid & 31;
    int ti  = warp * 4;
    int tj2 = lane * 2;

    if (tid < 64) { s1[tid] = 0.f; s2[tid] = 0.f; }

    ull acc[4] = {0, 0, 0, 0};

    // ---- Phase A: scores + s1/s2 over d-tiles ----
    for (int d0 = 0; d0 < DM; d0 += 64) {
        int dn = min(64, DM - d0);
        __syncthreads();
        for (int idx = tid; idx < 64 * 64; idx += 512) {
            int row = idx >> 6, d = idx & 63;
            float v  = (d < dn) ? X[row * DM + d0 + d] : 0.f;
            float wv = (d < dn) ? aw[2 * DM + d0 + d] : 0.f;
            xsT[d][row] = v;
            xw[d][row]  = v * wv;
        }
        __syncthreads();

#pragma unroll
        for (int rr = 0; rr < 4; rr++) {
            int row = ti + rr;
            float a1 = 0.f, a2 = 0.f;
            for (int d = lane; d < dn; d += 32) {
                float xv = xsT[d][row];
                a1 += xv * aw[d0 + d];
                a2 += xv * aw[DM + d0 + d];
            }
#pragma unroll
            for (int off = 16; off > 0; off >>= 1) {
                a1 += __shfl_down_sync(0xffffffffu, a1, off);
                a2 += __shfl_down_sync(0xffffffffu, a2, off);
            }
            if (lane == 0) { s1[row] += a1; s2[row] += a2; }
        }

#pragma unroll 4
        for (int d = 0; d < 64; d++) {
            float4 a4 = *(const float4*)&xsT[d][ti];
            ull bw = *(const ull*)&xw[d][tj2];
            fma2(acc[0], pk2(a4.x, a4.x), bw);
            fma2(acc[1], pk2(a4.y, a4.y), bw);
            fma2(acc[2], pk2(a4.z, a4.z), bw);
            fma2(acc[3], pk2(a4.w, a4.w), bw);
        }
    }
    __syncthreads();

    // ---- Phase B: softmax in-warp ----
    {
        float2 s2p = *(const float2*)&s2[tj2];
#pragma unroll
        for (int i = 0; i < 4; i++) {
            int row = ti + i;
            float base = s1[row] + ab;
            float v0, v1;
            upk2(acc[i], v0, v1);
            v0 += base + s2p.x;
            v1 += base + s2p.y;
            float l0 = (tj2     < len) ? v0 : -1e-9f;
            float l1 = (tj2 + 1 < len) ? v1 : -1e-9f;
            float mx = fmaxf(l0, l1);
#pragma unroll
            for (int off = 16; off > 0; off >>= 1)
                mx = fmaxf(mx, __shfl_xor_sync(0xffffffffu, mx, off));
            float e0 = __expf(l0 - mx), e1 = __expf(l1 - mx);
            float s = e0 + e1;
#pragma unroll
            for (int off = 16; off > 0; off >>= 1)
                s += __shfl_xor_sync(0xffffffffu, s, off);
            float inv = 1.f / s;
            xw[tj2][row]     = e0 * inv;
            xw[tj2 + 1][row] = e1 * inv;
        }
    }
    __syncthreads();

    // ---- Phase C: att = P @ x; out / residual ----
    float* xs = &xsT[0][0];
    for (int d0 = 0; d0 < DM; d0 += 64) {
        int dn = min(64, DM - d0);
        for (int idx = tid; idx < 64 * 32; idx += 512) {
            int row = idx >> 5, dp = idx & 31;
            float2 v = make_float2(0.f, 0.f);
            if (2 * dp < dn) v = *(const float2*)&X[row * DM + d0 + 2 * dp];
            *(float2*)&xs[row * 68 + 2 * dp] = v;
        }
        __syncthreads();
        ull acco[4] = {0, 0, 0, 0};
#pragma unroll 4
        for (int j = 0; j < 64; j++) {
            float4 p4 = *(const float4*)&xw[j][ti];
            ull xv = *(const ull*)&xs[j * 68 + tj2];
            fma2(acco[0], pk2(p4.x, p4.x), xv);
            fma2(acco[1], pk2(p4.y, p4.y), xv);
            fma2(acco[2], pk2(p4.z, p4.z), xv);
            fma2(acco[3], pk2(p4.w, p4.w), xv);
        }
        int d = d0 + tj2;
#pragma unroll
        for (int i = 0; i < 4; i++) {
            int row = ti + i;
            float o0, o1;
            upk2(acco[i], o0, o1);
            if (last) {
                if (d < DM)     dout[((size_t)batch * 64 + row) * DM + d]     = o0;
                if (d + 1 < DM) dout[((size_t)batch * 64 + row) * DM + d + 1] = o1;
            } else {
                float2 xv = *(const float2*)&xs[row * 68 + tj2];
                if (d < DM)     X[row * DM + d]     = o0 + xv.x;
                if (d + 1 < DM) X[row * DM + d + 1] = o1 + xv.y;
            }
        }
        __syncthreads();
    }
}

// ---------------------------------------------------------------------------
extern "C" void kernel_launch(void* const* d_in, const int* in_sizes, int n_in,
                              void* d_out, int out_size) {
    const int*   q1     = (const int*)d_in[0];
    const int*   q2     = (const int*)d_in[1];
    const int*   q1_len = (const int*)d_in[2];
    const int*   q2_len = (const int*)d_in[3];
    const int*   q1c    = (const int*)d_in[4];
    const int*   q2c    = (const int*)d_in[5];
    const float* wemb   = (const float*)d_in[6];
    const float* cemb   = (const float*)d_in[7];
    const float* cw3    = (const float*)d_in[8];
    const float* cb3    = (const float*)d_in[9];
    const float* cw4    = (const float*)d_in[10];
    const float* cb4    = (const float*)d_in[11];
    const float* cw5    = (const float*)d_in[12];
    const float* cb5    = (const float*)d_in[13];
    const float* hw_w   = (const float*)d_in[14];
    const float* hw_b   = (const float*)d_in[15];
    const float* attw   = (const float*)d_in[16];
    const float* attb   = (const float*)d_in[17];
    float* out = (float*)d_out;

    precomp_kernel<<<(60000 + 255) / 256, 256>>>(cemb, cw3, cw4, cw5);
    embed_kernel<<<NTOK, 160>>>(q1, q2, q1c, q2c, wemb, cb3, cb4, cb5);
    highway_kernel<<<dim3(8, 64), 256>>>(0, hw_w, hw_b);   // g_x -> g_y
    highway_kernel<<<dim3(8, 64), 256>>>(1, hw_w, hw_b);   // g_y -> g_x
    attn_kernel<<<128, 512>>>(q1_len, q2_len, attw, attb, 0, 0, out);
    attn_kernel<<<128, 512>>>(q1_len, q2_len, attw, attb, 1, 1, out);
}